// round 1
// baseline (speedup 1.0000x reference)
#include <cuda_runtime.h>
#include <math.h>

#define BB   128
#define NN   22
#define FF   448
#define HD   64
#define NPAIR (NN*NN)          // 484
#define NUPPER (NN*(NN-1)/2)   // 231

// Scratch (allowed: __device__ globals)
__device__ float g_proj[4 * BB * NN * HD];   // [m][b][i][c]  m: 0=u,1=v,2=p,3=q
__device__ float g_corr[BB * NPAIR];
__device__ float g_ab[2 * NN * HD];          // a (incl sb1), b

__device__ __forceinline__ float warpSum(float v) {
    #pragma unroll
    for (int o = 16; o; o >>= 1) v += __shfl_xor_sync(0xffffffffu, v, o);
    return v;
}

// ---------- Kernel E: emb projections a_i = emb_i @ sw1[0:64] + sb1, b_j = emb_j @ sw1[64:128]
__global__ void kernE(const float* __restrict__ emb, const float* __restrict__ sw1,
                      const float* __restrict__ sb1) {
    for (int o = threadIdx.x; o < 2 * NN * HD; o += blockDim.x) {
        int half = o / (NN * HD);
        int r = o - half * (NN * HD);
        int i = r / HD, c = r - i * HD;
        float acc = (half == 0) ? sb1[c] : 0.0f;
        const float* W = sw1 + half * HD * HD + c;
        const float* e = emb + i * HD;
        #pragma unroll 8
        for (int kk = 0; kk < HD; kk++) acc += e[kk] * W[kk * HD];
        g_ab[o] = acc;
    }
}

// ---------- Kernel A: per-batch stats + corr + projections (u,v,p,q)
__global__ __launch_bounds__(256) void kernA(const float* __restrict__ x,
                                             const float* __restrict__ cw1,
                                             const float* __restrict__ cb1,
                                             const float* __restrict__ sw1) {
    __shared__ float xs[NN * FF];
    __shared__ float s_mu[NN], s_istd[NN];
    const int b = blockIdx.x;
    const int tid = threadIdx.x;
    const int warp = tid >> 5, lane = tid & 31;

    // load x[b] (22x448)
    const float* xb = x + b * NN * FF;
    for (int idx = tid; idx < NN * FF; idx += 256) xs[idx] = xb[idx];
    __syncthreads();

    // per-row mean / unbiased std (warp per row)
    for (int i = warp; i < NN; i += 8) {
        float s = 0.f, sq = 0.f;
        const float* r = xs + i * FF;
        for (int k = lane; k < FF; k += 32) { float v = r[k]; s += v; sq += v * v; }
        s = warpSum(s); sq = warpSum(sq);
        if (lane == 0) {
            float mu = s / FF;
            float var = (sq - FF * mu * mu) / (FF - 1);
            var = fmaxf(var, 0.f);
            s_mu[i] = mu;
            s_istd[i] = 1.0f / (sqrtf(var) + 1e-8f);
        }
    }
    __syncthreads();

    // gram -> corr (upper incl diag, mirrored)
    for (int p = warp; p < NN * (NN + 1) / 2; p += 8) {
        int rem = p, i = 0;
        while (rem >= NN - i) { rem -= NN - i; i++; }
        int j = i + rem;
        float mi = s_mu[i], mj = s_mu[j];
        const float* ri = xs + i * FF;
        const float* rj = xs + j * FF;
        float cd = 0.f;
        for (int k = lane; k < FF; k += 32) cd += (ri[k] - mi) * (rj[k] - mj);
        cd = warpSum(cd);
        if (lane == 0) {
            float cv = fabsf(cd * s_istd[i] * s_istd[j]) * (1.0f / FF);
            g_corr[b * NPAIR + i * NN + j] = cv;
            g_corr[b * NPAIR + j * NN + i] = cv;
        }
    }

    // projections: thread t -> matrix m = t/64, column c = t%64
    const int m = tid >> 6, c = tid & 63;
    const float* Wp;
    if      (m == 0) Wp = cw1 + c;                     // rows [0,448)
    else if (m == 1) Wp = cw1 + 448 * HD + c;          // rows [448,896)
    else if (m == 2) Wp = sw1 + 128 * HD + c;          // rows [128,576)
    else             Wp = sw1 + 576 * HD + c;          // rows [576,1024)

    float acc[NN];
    #pragma unroll
    for (int i = 0; i < NN; i++) acc[i] = 0.f;

    for (int k = 0; k < FF; k++) {
        float wk = Wp[k * HD];
        #pragma unroll
        for (int i = 0; i < NN; i++) acc[i] += xs[i * FF + k] * wk;
    }

    // fold biases: cb1 into u; a(+sb1) into p; b into q
    float bias_u = (m == 0) ? cb1[c] : 0.f;
    float* outp = g_proj + ((size_t)m * BB + b) * NN * HD + c;
    #pragma unroll
    for (int i = 0; i < NN; i++) {
        float v = acc[i] + bias_u;
        if (m == 2) v += g_ab[i * HD + c];
        if (m == 3) v += g_ab[NN * HD + i * HD + c];
        outp[i * HD] = v;
    }
}

// ---------- Kernel B: per-pair MLPs + fusion
__global__ __launch_bounds__(512) void kernB(const float* __restrict__ cw2,
                                             const float* __restrict__ cb2,
                                             const float* __restrict__ lng,
                                             const float* __restrict__ lnb,
                                             const float* __restrict__ sw2,
                                             const float* __restrict__ sb2,
                                             const float* __restrict__ sw3,
                                             const float* __restrict__ sb3,
                                             const float* __restrict__ thr,
                                             const float* __restrict__ alpha_p,
                                             float* __restrict__ out) {
    __shared__ float us[NN * HD], vs[NN * HD], ps[NN * HD], qs[NN * HD];
    __shared__ float sw2s[HD * 32];
    __shared__ float corrs[NPAIR], adjs[NPAIR];
    __shared__ int   pl[NUPPER];
    __shared__ float cw2s[HD], lngs[HD], lnbs[HD], sb2s[32], sw3s[32];

    const int b = blockIdx.x;
    const int tid = threadIdx.x;
    const int warp = tid >> 5, lane = tid & 31;

    const float* pu = g_proj + ((size_t)0 * BB + b) * NN * HD;
    const float* pv = g_proj + ((size_t)1 * BB + b) * NN * HD;
    const float* pp = g_proj + ((size_t)2 * BB + b) * NN * HD;
    const float* pq = g_proj + ((size_t)3 * BB + b) * NN * HD;
    for (int idx = tid; idx < NN * HD; idx += 512) {
        us[idx] = pu[idx]; vs[idx] = pv[idx]; ps[idx] = pp[idx]; qs[idx] = pq[idx];
    }
    for (int idx = tid; idx < HD * 32; idx += 512) sw2s[idx] = sw2[idx];
    for (int idx = tid; idx < NPAIR; idx += 512) { corrs[idx] = g_corr[b * NPAIR + idx]; adjs[idx] = 0.f; }
    if (tid < HD) { cw2s[tid] = cw2[tid]; lngs[tid] = lng[tid]; lnbs[tid] = lnb[tid]; }
    if (tid < 32) { sb2s[tid] = sb2[tid]; sw3s[tid] = sw3[tid]; }
    if (tid < NPAIR) {
        int i = tid / NN, j = tid - i * NN;
        if (i < j) {
            int pos = i * (2 * NN - 1 - i) / 2 + (j - i - 1);
            pl[pos] = (i << 5) | j;
        }
    }
    const float tthr  = 1.0f / (1.0f + expf(-thr[0]));
    const float alpha = 1.0f / (1.0f + expf(-alpha_p[0]));
    const float cb2v = cb2[0], sb3v = sb3[0];
    __syncthreads();

    // Phase 1: semantic branch, i<j only
    for (int pidx = warp; pidx < NUPPER; pidx += 16) {
        int code = pl[pidx];
        int i = code >> 5, j = code & 31;
        float s0 = ps[i * HD + lane]      + qs[j * HD + lane];
        float s1 = ps[i * HD + 32 + lane] + qs[j * HD + 32 + lane];
        float mu = warpSum(s0 + s1) * (1.0f / HD);
        float d0 = s0 - mu, d1 = s1 - mu;
        float var = warpSum(d0 * d0 + d1 * d1) * (1.0f / HD);
        float rstd = rsqrtf(var + 1e-5f);
        float h1a = fmaxf(d0 * rstd * lngs[lane]      + lnbs[lane],      0.f);
        float h1b = fmaxf(d1 * rstd * lngs[32 + lane] + lnbs[32 + lane], 0.f);
        float h2 = sb2s[lane];
        #pragma unroll
        for (int c = 0; c < HD; c++) {
            float hv = __shfl_sync(0xffffffffu, (c < 32) ? h1a : h1b, c & 31);
            h2 += hv * sw2s[c * 32 + lane];
        }
        h2 = fmaxf(h2, 0.f);
        float z = warpSum(h2 * sw3s[lane]) + sb3v;
        float w_sem = 1.0f / (1.0f + expf(-z));
        float val = (w_sem > tthr) ? w_sem : 0.f;
        if (lane == 0) { adjs[i * NN + j] = val; adjs[j * NN + i] = val; }
    }
    __syncthreads();

    // Phase 2: correlation branch + fusion, all pairs
    float* ob = out + (size_t)b * NPAIR;
    for (int pidx = warp; pidx < NPAIR; pidx += 16) {
        int i = pidx / NN, j = pidx - i * NN;
        float h0 = fmaxf(us[i * HD + lane]      + vs[j * HD + lane],      0.f);
        float h1 = fmaxf(us[i * HD + 32 + lane] + vs[j * HD + 32 + lane], 0.f);
        float z = warpSum(h0 * cw2s[lane] + h1 * cw2s[32 + lane]) + cb2v;
        float w_corr = 1.0f / (1.0f + expf(-z));
        float eye = (i == j) ? 1.0f : 0.0f;
        float g_c = corrs[pidx] * w_corr + eye;
        float g_s = adjs[pidx] + eye;
        if (lane == 0) ob[pidx] = alpha * g_c + (1.0f - alpha) * g_s;
    }
}

extern "C" void kernel_launch(void* const* d_in, const int* in_sizes, int n_in,
                              void* d_out, int out_size) {
    const float* x       = (const float*)d_in[0];
    const float* cw1     = (const float*)d_in[1];
    const float* cb1     = (const float*)d_in[2];
    const float* cw2     = (const float*)d_in[3];
    const float* cb2     = (const float*)d_in[4];
    const float* emb     = (const float*)d_in[5];
    const float* sw1     = (const float*)d_in[6];
    const float* sb1     = (const float*)d_in[7];
    const float* ln_g    = (const float*)d_in[8];
    const float* ln_b    = (const float*)d_in[9];
    const float* sw2     = (const float*)d_in[10];
    const float* sb2     = (const float*)d_in[11];
    const float* sw3     = (const float*)d_in[12];
    const float* sb3     = (const float*)d_in[13];
    const float* thr     = (const float*)d_in[14];
    const float* alpha_p = (const float*)d_in[15];
    float* out = (float*)d_out;

    kernE<<<1, 256>>>(emb, sw1, sb1);
    kernA<<<BB, 256>>>(x, cw1, cb1, sw1);
    kernB<<<BB, 512>>>(cw2, cb2, ln_g, ln_b, sw2, sb2, sw3, sb3, thr, alpha_p, out);
}